// round 10
// baseline (speedup 1.0000x reference)
#include <cuda_runtime.h>
#include <cstdint>

// ---------------- problem constants ----------------
#define CI 4
#define CO 8
#define TT_ 8
#define DD 96
#define HH 96
#define WW 96
#define EPS 1e-5f
#define PLANE ((size_t)DD * HH * WW)

// ---------------- stats ----------------
#define NCHUNK 24
__device__ float g_partial_sum[32][NCHUNK];
__device__ float g_partial_sq[32][NCHUNK];
__device__ float g_mean[32];
__device__ float g_rstd[32];

__global__ void stats_partial(const float* __restrict__ x) {
    const int s = blockIdx.x, chunk = blockIdx.y;
    const float4* b4 = (const float4*)(x + (size_t)s * PLANE + (size_t)chunk * 4 * HH * WW);
    const int n4 = (4 * HH * WW) / 4;
    float sum = 0.f, sq = 0.f;
    for (int i = threadIdx.x; i < n4; i += blockDim.x) {
        float4 v = b4[i];
        sum += v.x + v.y + v.z + v.w;
        sq  += v.x * v.x + v.y * v.y + v.z * v.z + v.w * v.w;
    }
    __shared__ float ssum[8], ssq[8];
    #pragma unroll
    for (int off = 16; off > 0; off >>= 1) {
        sum += __shfl_down_sync(0xffffffffu, sum, off);
        sq  += __shfl_down_sync(0xffffffffu, sq, off);
    }
    const int warp = threadIdx.x >> 5, lane = threadIdx.x & 31;
    if (lane == 0) { ssum[warp] = sum; ssq[warp] = sq; }
    __syncthreads();
    if (threadIdx.x == 0) {
        float ts = 0.f, tq = 0.f;
        #pragma unroll
        for (int w = 0; w < 8; w++) { ts += ssum[w]; tq += ssq[w]; }
        g_partial_sum[s][chunk] = ts;
        g_partial_sq[s][chunk]  = tq;
    }
}

__global__ void stats_final() {
    const int s = threadIdx.x;
    float sum = 0.f, sq = 0.f;
    #pragma unroll
    for (int i = 0; i < NCHUNK; i++) { sum += g_partial_sum[s][i]; sq += g_partial_sq[s][i]; }
    const float inv = 1.0f / (float)PLANE;
    const float mean = sum * inv;
    const float var = sq * inv - mean * mean;
    g_mean[s] = mean;
    g_rstd[s] = rsqrtf(var + EPS);
}

// ---------------- mma helpers (baseline PTX only) ----------------
__device__ __forceinline__ uint32_t smem_u32(const void* p) {
    uint32_t a;
    asm("{ .reg .u64 t; cvta.to.shared.u64 t, %1; cvt.u32.u64 %0, t; }" : "=r"(a) : "l"(p));
    return a;
}
__device__ __forceinline__ uint32_t f2tf32(float f) {
    uint32_t r;
    asm("cvt.rna.tf32.f32 %0, %1;" : "=r"(r) : "f"(f));
    return r;
}
__device__ __forceinline__ void ldsm4(uint32_t& a0, uint32_t& a1, uint32_t& a2,
                                      uint32_t& a3, uint32_t addr) {
    asm volatile("ldmatrix.sync.aligned.m8n8.x4.shared.b16 {%0,%1,%2,%3}, [%4];"
                 : "=r"(a0), "=r"(a1), "=r"(a2), "=r"(a3) : "r"(addr));
}
__device__ __forceinline__ void mma_tf32(float* d, uint32_t a0, uint32_t a1,
                                         uint32_t a2, uint32_t a3,
                                         uint32_t b0, uint32_t b1) {
    asm volatile(
        "mma.sync.aligned.m16n8k8.row.col.f32.tf32.tf32.f32 "
        "{%0,%1,%2,%3}, {%4,%5,%6,%7}, {%8,%9}, {%0,%1,%2,%3};"
        : "+f"(d[0]), "+f"(d[1]), "+f"(d[2]), "+f"(d[3])
        : "r"(a0), "r"(a1), "r"(a2), "r"(a3), "r"(b0), "r"(b1));
}

// ---------------- conv kernel config ----------------
#define D_TILE 8
#define H_TILE 4
#define DL 10                      // D_TILE + 2
#define HL 6                       // H_TILE + 2
#define NROWS (DL * HL)            // 60 rows per phase
#define ROW_CHUNKS 100             // w' = -1..98, 16B each (zero-padded ends)
#define ROWB (ROW_CHUNKS * 16)     // 1600 B
#define IN_BYTES (NROWS * ROWB)    // 96000
#define B_OFF IN_BYTES
#define B_BYTES (9 * 2 * 32 * 8)   // 4608
#define SMEM_TOTAL (IN_BYTES + B_BYTES)   // 100608
#define NTH 256

__global__ __launch_bounds__(NTH, 1)
void conv4d_mma(const float* __restrict__ x, const float* __restrict__ wgt,
                const float* __restrict__ bias, float* __restrict__ out) {
    extern __shared__ char smem[];
    const uint32_t sbase = smem_u32(smem);
    const int tid = threadIdx.x;
    const int wid = tid >> 5, lane = tid & 31;

    const int bh = blockIdx.x % 24, bd = blockIdx.x / 24;   // 24 h-tiles x 12 d-tiles
    const int t = blockIdx.y;
    const int d0 = bd * D_TILE, h0 = bh * H_TILE;

    // ldmatrix lane offset (same mapping as validated R6 kernel)
    const int msub = lane & 7, quad = lane >> 3;
    const uint32_t lane_off = (uint32_t)(msub * 16 + (quad & 1) * 128 + (quad >> 1) * 16);

    // warp task split: odg = od pair group (0..3), wc0 = first w-chunk
    const int odg = wid & 3;
    const int wc0 = wid >> 2;      // tasks: wc = wc0 + 2*it, it=0..2

    // accumulators: [task 3][odl 2][oh 4][4 regs] -> persist across tt phases
    float acc[3][2][4][4];
    #pragma unroll
    for (int it = 0; it < 3; it++)
        #pragma unroll
        for (int o = 0; o < 2; o++)
            #pragma unroll
            for (int h = 0; h < 4; h++)
                #pragma unroll
                for (int r = 0; r < 4; r++) acc[it][o][h][r] = 0.f;

    #pragma unroll 1
    for (int tt = 0; tt < 3; tt++) {
        const int tp = t + tt - 1;
        if (tp < 0 || tp >= TT_) continue;      // uniform across CTA

        __syncthreads();   // previous phase fully consumed before overwrite

        float mean[CI], rstd[CI];
        #pragma unroll
        for (int ci = 0; ci < CI; ci++) {
            mean[ci] = g_mean[ci * TT_ + tp];
            rstd[ci] = g_rstd[ci * TT_ + tp];
        }

        // ---- load input slice: [dl 10][hl 6][chunk 100][ci 4] tf32, norm+ReLU+pad
        for (int i = tid; i < NROWS * ROW_CHUNKS; i += NTH) {
            const int row = i / ROW_CHUNKS;
            const int p = i - row * ROW_CHUNKS;
            const int wp = p - 1;
            const int dl = row / HL, hl = row - dl * HL;
            const int dp = d0 - 1 + dl, hp = h0 - 1 + hl;
            uint4 v = make_uint4(0u, 0u, 0u, 0u);
            if (((unsigned)wp < WW) & ((unsigned)dp < DD) & ((unsigned)hp < HH)) {
                const size_t sp = ((size_t)dp * HH + hp) * WW + wp;
                const float* xb = x + (size_t)tp * PLANE + sp;
                v.x = f2tf32(fmaxf(0.f, (xb[0]          - mean[0]) * rstd[0]));
                v.y = f2tf32(fmaxf(0.f, (xb[8 * PLANE]  - mean[1]) * rstd[1]));
                v.z = f2tf32(fmaxf(0.f, (xb[16 * PLANE] - mean[2]) * rstd[2]));
                v.w = f2tf32(fmaxf(0.f, (xb[24 * PLANE] - mean[3]) * rstd[3]));
            }
            *(uint4*)(smem + row * ROWB + p * 16) = v;
        }

        // ---- build B fragments for this tt: [kdkh 9][j 2][lane 32][b0,b1]
        for (int i = tid; i < B_BYTES / 4; i += NTH) {
            const int which = i & 1;
            const int l = (i >> 1) & 31;
            const int j = (i >> 6) & 1;
            const int kdkh = i >> 7;
            const int kd = kdkh / 3, kh = kdkh % 3;
            const int kl = (l & 3) + which * 4;
            const int kwg = j * 2 + (kl >> 2);
            const int ci = kl & 3, co = l >> 2;
            uint32_t v = 0u;
            if (kwg < 3)
                v = f2tf32(wgt[(co * CI + ci) * 81 + tt * 27 + kd * 9 + kh * 3 + kwg]);
            *(uint32_t*)(smem + B_OFF + i * 4) = v;
        }
        __syncthreads();

        // ---- preload B fragments once per phase (36 regs) ----
        uint2 bf[9][2];
        const uint2* bsm = (const uint2*)(smem + B_OFF);
        #pragma unroll
        for (int tp9 = 0; tp9 < 9; tp9++)
            #pragma unroll
            for (int j = 0; j < 2; j++)
                bf[tp9][j] = bsm[(tp9 * 2 + j) * 32 + lane];

        // ---- compute: walk input rows once; each ldsm feeds up to 6 MMAs ----
        #pragma unroll
        for (int it = 0; it < 3; it++) {
            const int wc = wc0 + 2 * it;
            #pragma unroll
            for (int r = 0; r < 4; r++) {            // dl = odg*2 + r
                #pragma unroll
                for (int hl = 0; hl < 6; hl++) {
                    const uint32_t raddr = sbase
                        + (uint32_t)(((odg * 2 + r) * HL + hl) * ROWB + wc * 256)
                        + lane_off;
                    uint32_t a0, a1, a2, a3, c0, c1, c2, c3;
                    ldsm4(a0, a1, a2, a3, raddr);
                    ldsm4(c0, c1, c2, c3, raddr + 32);
                    #pragma unroll
                    for (int kd = 0; kd < 3; kd++) {
                        const int odl = r - kd;         // local od within pair
                        if (odl < 0 || odl > 1) continue;
                        #pragma unroll
                        for (int kh = 0; kh < 3; kh++) {
                            const int oh = hl - kh;
                            if (oh < 0 || oh > 3) continue;
                            mma_tf32(acc[it][odl][oh], a0, a1, a2, a3,
                                     bf[kd * 3 + kh][0].x, bf[kd * 3 + kh][0].y);
                            mma_tf32(acc[it][odl][oh], c0, c1, c2, c3,
                                     bf[kd * 3 + kh][1].x, bf[kd * 3 + kh][1].y);
                        }
                    }
                }
            }
        }
    }

    // ---- epilogue: bias add + store ----
    const int co0 = (lane & 3) * 2;
    const int w8 = lane >> 2;
    const float bv0 = bias[co0], bv1 = bias[co0 + 1];
    #pragma unroll
    for (int it = 0; it < 3; it++) {
        const int wc = wc0 + 2 * it;
        #pragma unroll
        for (int odl = 0; odl < 2; odl++) {
            const int gd = d0 + odg * 2 + odl;
            #pragma unroll
            for (int oh = 0; oh < 4; oh++) {
                const int gh = h0 + oh;
                const int wa = wc * 16 + w8;
                const size_t sp = (((size_t)t * DD + gd) * HH + gh) * WW + wa;
                const float* a = acc[it][odl][oh];
                out[(size_t)(co0    ) * (TT_ * PLANE) + sp]     = a[0] + bv0;
                out[(size_t)(co0 + 1) * (TT_ * PLANE) + sp]     = a[1] + bv1;
                out[(size_t)(co0    ) * (TT_ * PLANE) + sp + 8] = a[2] + bv0;
                out[(size_t)(co0 + 1) * (TT_ * PLANE) + sp + 8] = a[3] + bv1;
            }
        }
    }
}

// ---------------------------------------------------------------------------
extern "C" void kernel_launch(void* const* d_in, const int* in_sizes, int n_in,
                              void* d_out, int out_size) {
    const float* x = (const float*)d_in[0];
    const float* w = (const float*)d_in[1];
    const float* b = (const float*)d_in[2];
    float* out = (float*)d_out;

    cudaFuncSetAttribute(conv4d_mma, cudaFuncAttributeMaxDynamicSharedMemorySize,
                         SMEM_TOTAL);

    stats_partial<<<dim3(32, NCHUNK), 256>>>(x);
    stats_final<<<1, 32>>>();
    conv4d_mma<<<dim3(12 * 24, TT_), NTH, SMEM_TOTAL>>>(x, w, b, out);
}

// round 12
// speedup vs baseline: 1.6976x; 1.6976x over previous
#include <cuda_runtime.h>
#include <cuda_fp16.h>
#include <cstdint>

// ---------------- problem constants ----------------
#define CI 4
#define CO 8
#define TT_ 8
#define DD 96
#define HH 96
#define WW 96
#define EPS 1e-5f
#define PLANE ((size_t)DD * HH * WW)

// ---------------- stats ----------------
#define NCHUNK 24
__device__ float g_partial_sum[32][NCHUNK];
__device__ float g_partial_sq[32][NCHUNK];
__device__ float g_mean[32];
__device__ float g_rstd[32];

__global__ void stats_partial(const float* __restrict__ x) {
    const int s = blockIdx.x, chunk = blockIdx.y;
    const float4* b4 = (const float4*)(x + (size_t)s * PLANE + (size_t)chunk * 4 * HH * WW);
    const int n4 = (4 * HH * WW) / 4;
    float sum = 0.f, sq = 0.f;
    for (int i = threadIdx.x; i < n4; i += blockDim.x) {
        float4 v = b4[i];
        sum += v.x + v.y + v.z + v.w;
        sq  += v.x * v.x + v.y * v.y + v.z * v.z + v.w * v.w;
    }
    __shared__ float ssum[8], ssq[8];
    #pragma unroll
    for (int off = 16; off > 0; off >>= 1) {
        sum += __shfl_down_sync(0xffffffffu, sum, off);
        sq  += __shfl_down_sync(0xffffffffu, sq, off);
    }
    const int warp = threadIdx.x >> 5, lane = threadIdx.x & 31;
    if (lane == 0) { ssum[warp] = sum; ssq[warp] = sq; }
    __syncthreads();
    if (threadIdx.x == 0) {
        float ts = 0.f, tq = 0.f;
        #pragma unroll
        for (int w = 0; w < 8; w++) { ts += ssum[w]; tq += ssq[w]; }
        g_partial_sum[s][chunk] = ts;
        g_partial_sq[s][chunk]  = tq;
    }
}

__global__ void stats_final() {
    const int s = threadIdx.x;
    float sum = 0.f, sq = 0.f;
    #pragma unroll
    for (int i = 0; i < NCHUNK; i++) { sum += g_partial_sum[s][i]; sq += g_partial_sq[s][i]; }
    const float inv = 1.0f / (float)PLANE;
    const float mean = sum * inv;
    const float var = sq * inv - mean * mean;
    g_mean[s] = mean;
    g_rstd[s] = rsqrtf(var + EPS);
}

// ---------------- mma helpers (baseline PTX only) ----------------
__device__ __forceinline__ uint32_t smem_u32(const void* p) {
    uint32_t a;
    asm("{ .reg .u64 t; cvta.to.shared.u64 t, %1; cvt.u32.u64 %0, t; }" : "=r"(a) : "l"(p));
    return a;
}
__device__ __forceinline__ void ldsm4(uint32_t& a0, uint32_t& a1, uint32_t& a2,
                                      uint32_t& a3, uint32_t addr) {
    asm volatile("ldmatrix.sync.aligned.m8n8.x4.shared.b16 {%0,%1,%2,%3}, [%4];"
                 : "=r"(a0), "=r"(a1), "=r"(a2), "=r"(a3) : "r"(addr));
}
__device__ __forceinline__ void mma_f16(float* d, uint32_t a0, uint32_t a1,
                                        uint32_t a2, uint32_t a3,
                                        uint32_t b0, uint32_t b1) {
    asm volatile(
        "mma.sync.aligned.m16n8k16.row.col.f32.f16.f16.f32 "
        "{%0,%1,%2,%3}, {%4,%5,%6,%7}, {%8,%9}, {%0,%1,%2,%3};"
        : "+f"(d[0]), "+f"(d[1]), "+f"(d[2]), "+f"(d[3])
        : "r"(a0), "r"(a1), "r"(a2), "r"(a3), "r"(b0), "r"(b1));
}

// ---------------- conv kernel config ----------------
#define D_TILE 4
#define H_TILE 4
#define DL 6
#define HL 6
#define NROWS (DL * HL)            // 36 rows
#define ROW_PTS 100                // s = 0..99 (input w = s-1; s>=98 zero)
#define ROWB (ROW_PTS * 8)         // 800 B (f16 x 4ci = 8B per point)
#define IN_BYTES (NROWS * ROWB)    // 28800
#define B_OFF IN_BYTES
#define B_BYTES (9 * 2 * 32 * 8)   // 4608: [tap 9][parity 2][lane 32] uint2
#define SMEM_TOTAL (IN_BYTES + B_BYTES)   // 33408
#define NTH 256

__global__ __launch_bounds__(NTH, 2)
void conv4d_mma(const float* __restrict__ x, const float* __restrict__ wgt,
                const float* __restrict__ bias, float* __restrict__ out) {
    extern __shared__ char smem[];
    const uint32_t sbase = smem_u32(smem);
    const int tid = threadIdx.x;
    const int wid = tid >> 5, lane = tid & 31;

    const int bh = blockIdx.x % 24, bd = blockIdx.x / 24;
    const int t = blockIdx.y;
    const int d0 = bd * D_TILE, h0 = bh * H_TILE;

    // ldmatrix lane offset: rows at 16B stride (point pairs), k8-15 = +16B
    const uint32_t lane_off = (uint32_t)(((lane & 15) + (lane >> 4)) * 16);

    // accumulators: [pp 2][wc 3][parity 2][4 regs] = 48 regs, persist over tt
    float acc[2][3][2][4];
    #pragma unroll
    for (int p = 0; p < 2; p++)
        #pragma unroll
        for (int w = 0; w < 3; w++)
            #pragma unroll
            for (int q = 0; q < 2; q++)
                #pragma unroll
                for (int r = 0; r < 4; r++) acc[p][w][q][r] = 0.f;

    #pragma unroll 1
    for (int tt = 0; tt < 3; tt++) {
        const int tp = t + tt - 1;
        if (tp < 0 || tp >= TT_) continue;      // uniform across CTA

        __syncthreads();   // previous phase fully consumed before overwrite

        float mean[CI], rstd[CI];
        #pragma unroll
        for (int ci = 0; ci < CI; ci++) {
            mean[ci] = g_mean[ci * TT_ + tp];
            rstd[ci] = g_rstd[ci * TT_ + tp];
        }

        // ---- load input slice: [dl 6][hl 6][s 100][ci 4] f16, norm+ReLU+pad
        for (int i = tid; i < NROWS * ROW_PTS; i += NTH) {
            const int row = i / ROW_PTS;
            const int s = i - row * ROW_PTS;
            const int wp = s - 1;
            const int dl = row / HL, hl = row - dl * HL;
            const int dp = d0 - 1 + dl, hp = h0 - 1 + hl;
            uint2 v = make_uint2(0u, 0u);
            if (((unsigned)wp < WW) & ((unsigned)dp < DD) & ((unsigned)hp < HH)) {
                const size_t sp = ((size_t)dp * HH + hp) * WW + wp;
                const float* xb = x + (size_t)tp * PLANE + sp;
                const float f0 = fmaxf(0.f, (xb[0]          - mean[0]) * rstd[0]);
                const float f1 = fmaxf(0.f, (xb[8 * PLANE]  - mean[1]) * rstd[1]);
                const float f2 = fmaxf(0.f, (xb[16 * PLANE] - mean[2]) * rstd[2]);
                const float f3 = fmaxf(0.f, (xb[24 * PLANE] - mean[3]) * rstd[3]);
                half2 h01 = __floats2half2_rn(f0, f1);
                half2 h23 = __floats2half2_rn(f2, f3);
                v.x = *(uint32_t*)&h01;
                v.y = *(uint32_t*)&h23;
            }
            *(uint2*)(smem + row * ROWB + s * 8) = v;
        }

        // ---- build B fragments: [tap 9][parity 2][lane 32][2 regs] f16
        // k = j*8 + (lane&3)*2 + i;  pt = k>>2; ci = k&3; kw = pt - parity
        for (int i = tid; i < B_BYTES / 4; i += NTH) {   // 1152 u32
            const int j = i & 1;
            const int l = (i >> 1) & 31;
            const int P = (i >> 6) & 1;
            const int tap = i >> 7;
            const int kd = tap / 3, kh = tap % 3;
            const int co = l >> 2;
            float f[2];
            #pragma unroll
            for (int hv = 0; hv < 2; hv++) {
                const int k = j * 8 + (l & 3) * 2 + hv;
                const int pt = k >> 2, ci = k & 3;
                const int kw = pt - P;
                f[hv] = (kw >= 0 && kw < 3)
                    ? wgt[(co * CI + ci) * 81 + tt * 27 + kd * 9 + kh * 3 + kw]
                    : 0.f;
            }
            half2 hh = __floats2half2_rn(f[0], f[1]);
            *(uint32_t*)(smem + B_OFF + i * 4) = *(uint32_t*)&hh;
        }
        __syncthreads();

        // ---- preload B fragments (36 regs) ----
        uint2 bf[9][2];
        const uint2* bsm = (const uint2*)(smem + B_OFF);
        #pragma unroll
        for (int tp9 = 0; tp9 < 9; tp9++)
            #pragma unroll
            for (int P = 0; P < 2; P++)
                bf[tp9][P] = bsm[(tp9 * 2 + P) * 32 + lane];

        // ---- compute: 1 ldsm feeds even+odd parity MMAs (k16) ----
        #pragma unroll
        for (int pp = 0; pp < 2; pp++) {
            const int pid = wid * 2 + pp;
            const int od = pid >> 2, oh = pid & 3;
            #pragma unroll
            for (int wc = 0; wc < 3; wc++) {
                #pragma unroll
                for (int kd = 0; kd < 3; kd++) {
                    #pragma unroll
                    for (int kh = 0; kh < 3; kh++) {
                        const uint32_t raddr = sbase + lane_off
                            + (uint32_t)(((od + kd) * HL + (oh + kh)) * ROWB
                                         + wc * 256);
                        uint32_t a0, a1, a2, a3;
                        ldsm4(a0, a1, a2, a3, raddr);
                        mma_f16(acc[pp][wc][0], a0, a1, a2, a3,
                                bf[kd * 3 + kh][0].x, bf[kd * 3 + kh][0].y);
                        mma_f16(acc[pp][wc][1], a0, a1, a2, a3,
                                bf[kd * 3 + kh][1].x, bf[kd * 3 + kh][1].y);
                    }
                }
            }
        }
    }

    // ---- epilogue: pack even/odd into float2 stores + bias ----
    const int co0 = (lane & 3) * 2;
    const float bv0 = bias[co0], bv1 = bias[co0 + 1];
    #pragma unroll
    for (int pp = 0; pp < 2; pp++) {
        const int pid = wid * 2 + pp;
        const int od = pid >> 2, oh = pid & 3;
        const int gd = d0 + od, gh = h0 + oh;
        #pragma unroll
        for (int wc = 0; wc < 3; wc++) {
            const int wb = wc * 32 + 2 * (lane >> 2);   // even, pairs with wb+1
            const size_t sp = (((size_t)t * DD + gd) * HH + gh) * WW + wb;
            const float* aE = acc[pp][wc][0];
            const float* aO = acc[pp][wc][1];
            float2 v;
            v.x = aE[0] + bv0; v.y = aO[0] + bv0;
            *(float2*)(out + (size_t)co0 * (TT_ * PLANE) + sp) = v;
            v.x = aE[1] + bv1; v.y = aO[1] + bv1;
            *(float2*)(out + (size_t)(co0 + 1) * (TT_ * PLANE) + sp) = v;
            v.x = aE[2] + bv0; v.y = aO[2] + bv0;
            *(float2*)(out + (size_t)co0 * (TT_ * PLANE) + sp + 16) = v;
            v.x = aE[3] + bv1; v.y = aO[3] + bv1;
            *(float2*)(out + (size_t)(co0 + 1) * (TT_ * PLANE) + sp + 16) = v;
        }
    }
}

// ---------------------------------------------------------------------------
extern "C" void kernel_launch(void* const* d_in, const int* in_sizes, int n_in,
                              void* d_out, int out_size) {
    const float* x = (const float*)d_in[0];
    const float* w = (const float*)d_in[1];
    const float* b = (const float*)d_in[2];
    float* out = (float*)d_out;

    cudaFuncSetAttribute(conv4d_mma, cudaFuncAttributeMaxDynamicSharedMemorySize,
                         SMEM_TOTAL);

    stats_partial<<<dim3(32, NCHUNK), 256>>>(x);
    stats_final<<<1, 32>>>();
    conv4d_mma<<<dim3(24 * 24, TT_), NTH, SMEM_TOTAL>>>(x, w, b, out);
}

// round 14
// speedup vs baseline: 3.2007x; 1.8855x over previous
#include <cuda_runtime.h>
#include <cuda_fp16.h>
#include <cstdint>

// ---------------- problem constants ----------------
#define CI 4
#define CO 8
#define TT_ 8
#define DD 96
#define HH 96
#define WW 96
#define EPS 1e-5f
#define PLANE ((size_t)DD * HH * WW)

// ---------------- stats ----------------
#define NCHUNK 24
__device__ float g_partial_sum[32][NCHUNK];
__device__ float g_partial_sq[32][NCHUNK];
__device__ float g_mean[32];
__device__ float g_rstd[32];

// normalized f16 input, zero-padded: [t][d 0..99][h 0..99][w 0..99] x (4ci f16 = 8B)
// static __device__ => zero-initialized; borders never written => stay zero.
__device__ __align__(16) uint2 g_xn[TT_][100][100][100];
// B fragments per temporal tap: [tt][tap 9][parity 2][lane 32] (2 f16x2 regs)
__device__ uint2 g_bfrag[3][9][2][32];

__global__ void stats_partial(const float* __restrict__ x) {
    const int s = blockIdx.x, chunk = blockIdx.y;
    const float4* b4 = (const float4*)(x + (size_t)s * PLANE + (size_t)chunk * 4 * HH * WW);
    const int n4 = (4 * HH * WW) / 4;
    float sum = 0.f, sq = 0.f;
    for (int i = threadIdx.x; i < n4; i += blockDim.x) {
        float4 v = b4[i];
        sum += v.x + v.y + v.z + v.w;
        sq  += v.x * v.x + v.y * v.y + v.z * v.z + v.w * v.w;
    }
    __shared__ float ssum[8], ssq[8];
    #pragma unroll
    for (int off = 16; off > 0; off >>= 1) {
        sum += __shfl_down_sync(0xffffffffu, sum, off);
        sq  += __shfl_down_sync(0xffffffffu, sq, off);
    }
    const int warp = threadIdx.x >> 5, lane = threadIdx.x & 31;
    if (lane == 0) { ssum[warp] = sum; ssq[warp] = sq; }
    __syncthreads();
    if (threadIdx.x == 0) {
        float ts = 0.f, tq = 0.f;
        #pragma unroll
        for (int w = 0; w < 8; w++) { ts += ssum[w]; tq += ssq[w]; }
        g_partial_sum[s][chunk] = ts;
        g_partial_sq[s][chunk]  = tq;
    }
}

__global__ void stats_final() {
    const int s = threadIdx.x;
    float sum = 0.f, sq = 0.f;
    #pragma unroll
    for (int i = 0; i < NCHUNK; i++) { sum += g_partial_sum[s][i]; sq += g_partial_sq[s][i]; }
    const float inv = 1.0f / (float)PLANE;
    const float mean = sum * inv;
    const float var = sq * inv - mean * mean;
    g_mean[s] = mean;
    g_rstd[s] = rsqrtf(var + EPS);
}

// ---------------- prepass: normalize + ReLU + f16 pack into padded scratch ----
__global__ __launch_bounds__(256)
void normalize_f16(const float* __restrict__ x) {
    const int d = blockIdx.x % DD, t = blockIdx.x / DD;
    float mean[CI], rstd[CI];
    #pragma unroll
    for (int ci = 0; ci < CI; ci++) {
        mean[ci] = g_mean[ci * TT_ + t];
        rstd[ci] = g_rstd[ci * TT_ + t];
    }
    const float* xb = x + (size_t)t * PLANE + (size_t)d * (HH * WW);
    for (int i = threadIdx.x; i < HH * WW; i += 256) {
        const int h = i / WW, w = i % WW;
        const float f0 = fmaxf(0.f, (xb[i]              - mean[0]) * rstd[0]);
        const float f1 = fmaxf(0.f, (xb[i + 8  * PLANE] - mean[1]) * rstd[1]);
        const float f2 = fmaxf(0.f, (xb[i + 16 * PLANE] - mean[2]) * rstd[2]);
        const float f3 = fmaxf(0.f, (xb[i + 24 * PLANE] - mean[3]) * rstd[3]);
        half2 h01 = __floats2half2_rn(f0, f1);
        half2 h23 = __floats2half2_rn(f2, f3);
        uint2 v;
        v.x = *(uint32_t*)&h01;
        v.y = *(uint32_t*)&h23;
        g_xn[t][d + 1][h + 1][w + 1] = v;
    }
}

// ---------------- prepass: B fragments ----------------
__global__ void build_bfrag(const float* __restrict__ wgt) {
    // 3*9*2*32 = 1728 uint2 elements
    for (int e = threadIdx.x; e < 1728; e += 256) {
        const int l = e & 31;
        const int P = (e >> 5) & 1;
        const int tap = (e >> 6) % 9;
        const int tt = e / (9 * 64);
        const int kd = tap / 3, kh = tap % 3;
        const int co = l >> 2;
        float f[4];
        #pragma unroll
        for (int j = 0; j < 2; j++)
            #pragma unroll
            for (int hv = 0; hv < 2; hv++) {
                const int k = j * 8 + (l & 3) * 2 + hv;
                const int pt = k >> 2, ci = k & 3;
                const int kw = pt - P;
                f[j * 2 + hv] = (kw >= 0 && kw < 3)
                    ? wgt[(co * CI + ci) * 81 + tt * 27 + kd * 9 + kh * 3 + kw]
                    : 0.f;
            }
        half2 h0 = __floats2half2_rn(f[0], f[1]);
        half2 h1 = __floats2half2_rn(f[2], f[3]);
        uint2 v;
        v.x = *(uint32_t*)&h0;
        v.y = *(uint32_t*)&h1;
        g_bfrag[tt][tap][P][l] = v;
    }
}

// ---------------- mma helpers (baseline PTX only) ----------------
__device__ __forceinline__ uint32_t smem_u32(const void* p) {
    uint32_t a;
    asm("{ .reg .u64 t; cvta.to.shared.u64 t, %1; cvt.u32.u64 %0, t; }" : "=r"(a) : "l"(p));
    return a;
}
__device__ __forceinline__ void ldsm4(uint32_t& a0, uint32_t& a1, uint32_t& a2,
                                      uint32_t& a3, uint32_t addr) {
    asm volatile("ldmatrix.sync.aligned.m8n8.x4.shared.b16 {%0,%1,%2,%3}, [%4];"
                 : "=r"(a0), "=r"(a1), "=r"(a2), "=r"(a3) : "r"(addr));
}
__device__ __forceinline__ void mma_f16(float* d, uint32_t a0, uint32_t a1,
                                        uint32_t a2, uint32_t a3,
                                        uint32_t b0, uint32_t b1) {
    asm volatile(
        "mma.sync.aligned.m16n8k16.row.col.f32.f16.f16.f32 "
        "{%0,%1,%2,%3}, {%4,%5,%6,%7}, {%8,%9}, {%0,%1,%2,%3};"
        : "+f"(d[0]), "+f"(d[1]), "+f"(d[2]), "+f"(d[3])
        : "r"(a0), "r"(a1), "r"(a2), "r"(a3), "r"(b0), "r"(b1));
}
__device__ __forceinline__ void cpasync16(uint32_t dst, const void* src) {
    asm volatile("cp.async.cg.shared.global [%0], [%1], 16;"
                 :: "r"(dst), "l"(__cvta_generic_to_global(src)) : "memory");
}
__device__ __forceinline__ void cp_commit() {
    asm volatile("cp.async.commit_group;" ::: "memory");
}
template <int N>
__device__ __forceinline__ void cp_wait() {
    asm volatile("cp.async.wait_group %0;" :: "n"(N) : "memory");
}

// ---------------- conv kernel config ----------------
#define D_TILE 4
#define H_TILE 4
#define DL 6
#define HL 6
#define NROWS (DL * HL)            // 36 rows
#define ROW_PTS 100                // s = 0..99
#define ROWB (ROW_PTS * 8)         // 800 B
#define SLICE_BYTES (NROWS * ROWB) // 28800
#define N_CHUNK (NROWS * (ROW_PTS / 2))   // 1800 x 16B per phase
#define SMEM_TOTAL (2 * SLICE_BYTES)      // 57600 (double buffer)
#define NTH 256

__global__ __launch_bounds__(NTH, 2)
void conv4d_mma(const float* __restrict__ bias, float* __restrict__ out) {
    extern __shared__ char smem[];
    const uint32_t sbase = smem_u32(smem);
    const int tid = threadIdx.x;
    const int wid = tid >> 5, lane = tid & 31;

    const int bh = blockIdx.x % 24, bd = blockIdx.x / 24;
    const int t = blockIdx.y;
    const int d0 = bd * D_TILE, h0 = bh * H_TILE;

    const uint32_t lane_off = (uint32_t)(((lane & 15) + (lane >> 4)) * 16);

    // valid phases
    int phases[3], nph = 0;
    #pragma unroll
    for (int tt = 0; tt < 3; tt++) {
        const int tp = t + tt - 1;
        if (tp >= 0 && tp < TT_) phases[nph++] = tt;
    }

    // loader: issue all 1800 cp.async 16B chunks of one phase into a buffer
    auto issue_phase = [&](int tt, int buf) {
        const int tp = t + tt - 1;
        const uint32_t base = sbase + buf * SLICE_BYTES;
        #pragma unroll 1
        for (int i = tid; i < N_CHUNK; i += NTH) {
            const int row = i / 50;
            const int c = i - row * 50;
            const int dl = row / HL, hl = row - dl * HL;
            // padded indices: (d0-1+dl)+1 = d0+dl
            cpasync16(base + (uint32_t)(row * ROWB + c * 16),
                      &g_xn[tp][d0 + dl][h0 + hl][2 * c]);
        }
        cp_commit();
    };

    // accumulators: [pp 2][wc 3][parity 2][4]
    float acc[2][3][2][4];
    #pragma unroll
    for (int p = 0; p < 2; p++)
        #pragma unroll
        for (int w = 0; w < 3; w++)
            #pragma unroll
            for (int q = 0; q < 2; q++)
                #pragma unroll
                for (int r = 0; r < 4; r++) acc[p][w][q][r] = 0.f;

    // prologue: prefetch first (and second) phase
    issue_phase(phases[0], 0);
    if (nph > 1) issue_phase(phases[1], 1);

    const int pid = wid * 2;     // base (od,oh) pair id
    #pragma unroll 1
    for (int i = 0; i < nph; i++) {
        if (i < nph - 1) cp_wait<1>(); else cp_wait<0>();
        __syncthreads();

        const int tt = phases[i];
        // B fragments from global (L1/L2-resident)
        uint2 bf[9][2];
        #pragma unroll
        for (int tp9 = 0; tp9 < 9; tp9++) {
            bf[tp9][0] = g_bfrag[tt][tp9][0][lane];
            bf[tp9][1] = g_bfrag[tt][tp9][1][lane];
        }

        const uint32_t bufb = sbase + (uint32_t)((i & 1) * SLICE_BYTES) + lane_off;

        #pragma unroll
        for (int pp = 0; pp < 2; pp++) {
            const int od = (pid + pp) >> 2, oh = (pid + pp) & 3;
            #pragma unroll
            for (int wc = 0; wc < 3; wc++) {
                #pragma unroll
                for (int kd = 0; kd < 3; kd++) {
                    #pragma unroll
                    for (int kh = 0; kh < 3; kh++) {
                        const uint32_t raddr = bufb
                            + (uint32_t)(((od + kd) * HL + (oh + kh)) * ROWB
                                         + wc * 256);
                        uint32_t a0, a1, a2, a3;
                        ldsm4(a0, a1, a2, a3, raddr);
                        mma_f16(acc[pp][wc][0], a0, a1, a2, a3,
                                bf[kd * 3 + kh][0].x, bf[kd * 3 + kh][0].y);
                        mma_f16(acc[pp][wc][1], a0, a1, a2, a3,
                                bf[kd * 3 + kh][1].x, bf[kd * 3 + kh][1].y);
                    }
                }
            }
        }

        // refill the buffer just consumed with phase i+2
        if (i + 2 < nph) {
            __syncthreads();
            issue_phase(phases[i + 2], i & 1);
        }
    }

    // ---- epilogue: pack even/odd into float2 stores + bias ----
    const int co0 = (lane & 3) * 2;
    const float bv0 = bias[co0], bv1 = bias[co0 + 1];
    #pragma unroll
    for (int pp = 0; pp < 2; pp++) {
        const int od = (pid + pp) >> 2, oh = (pid + pp) & 3;
        const int gd = d0 + od, gh = h0 + oh;
        #pragma unroll
        for (int wc = 0; wc < 3; wc++) {
            const int wb = wc * 32 + 2 * (lane >> 2);
            const size_t sp = (((size_t)t * DD + gd) * HH + gh) * WW + wb;
            const float* aE = acc[pp][wc][0];
            const float* aO = acc[pp][wc][1];
            float2 v;
            v.x = aE[0] + bv0; v.y = aO[0] + bv0;
            *(float2*)(out + (size_t)co0 * (TT_ * PLANE) + sp) = v;
            v.x = aE[1] + bv1; v.y = aO[1] + bv1;
            *(float2*)(out + (size_t)(co0 + 1) * (TT_ * PLANE) + sp) = v;
            v.x = aE[2] + bv0; v.y = aO[2] + bv0;
            *(float2*)(out + (size_t)co0 * (TT_ * PLANE) + sp + 16) = v;
            v.x = aE[3] + bv1; v.y = aO[3] + bv1;
            *(float2*)(out + (size_t)(co0 + 1) * (TT_ * PLANE) + sp + 16) = v;
        }
    }
}

// ---------------------------------------------------------------------------
extern "C" void kernel_launch(void* const* d_in, const int* in_sizes, int n_in,
                              void* d_out, int out_size) {
    const float* x = (const float*)d_in[0];
    const float* w = (const float*)d_in[1];
    const float* b = (const float*)d_in[2];
    float* out = (float*)d_out;

    cudaFuncSetAttribute(conv4d_mma, cudaFuncAttributeMaxDynamicSharedMemorySize,
                         SMEM_TOTAL);

    stats_partial<<<dim3(32, NCHUNK), 256>>>(x);
    stats_final<<<1, 32>>>();
    normalize_f16<<<TT_ * DD, 256>>>(x);
    build_bfrag<<<1, 256>>>(w);
    conv4d_mma<<<dim3(24 * 24, TT_), NTH, SMEM_TOTAL>>>(b, out);
}

// round 16
// speedup vs baseline: 3.3132x; 1.0351x over previous
#include <cuda_runtime.h>
#include <cuda_fp16.h>
#include <cstdint>

// ---------------- problem constants ----------------
#define CI 4
#define CO 8
#define TT_ 8
#define DD 96
#define HH 96
#define WW 96
#define EPS 1e-5f
#define PLANE ((size_t)DD * HH * WW)

// ---------------- stats ----------------
#define NCHUNK 24
__device__ float g_partial_sum[32][NCHUNK];
__device__ float g_partial_sq[32][NCHUNK];
__device__ float g_mean[32];
__device__ float g_rstd[32];

// normalized f16 input, zero-padded: [t][d 0..99][h 0..99][w 0..99] x (4ci f16 = 8B)
__device__ __align__(16) uint2 g_xn[TT_][100][100][100];
// B fragments: [tt][tap 9][parity 2][lane 32]
__device__ uint2 g_bfrag[3][9][2][32];

__global__ void stats_partial(const float* __restrict__ x) {
    const int s = blockIdx.x, chunk = blockIdx.y;
    const float4* b4 = (const float4*)(x + (size_t)s * PLANE + (size_t)chunk * 4 * HH * WW);
    const int n4 = (4 * HH * WW) / 4;
    float sum = 0.f, sq = 0.f;
    for (int i = threadIdx.x; i < n4; i += blockDim.x) {
        float4 v = b4[i];
        sum += v.x + v.y + v.z + v.w;
        sq  += v.x * v.x + v.y * v.y + v.z * v.z + v.w * v.w;
    }
    __shared__ float ssum[8], ssq[8];
    #pragma unroll
    for (int off = 16; off > 0; off >>= 1) {
        sum += __shfl_down_sync(0xffffffffu, sum, off);
        sq  += __shfl_down_sync(0xffffffffu, sq, off);
    }
    const int warp = threadIdx.x >> 5, lane = threadIdx.x & 31;
    if (lane == 0) { ssum[warp] = sum; ssq[warp] = sq; }
    __syncthreads();
    if (threadIdx.x == 0) {
        float ts = 0.f, tq = 0.f;
        #pragma unroll
        for (int w = 0; w < 8; w++) { ts += ssum[w]; tq += ssq[w]; }
        g_partial_sum[s][chunk] = ts;
        g_partial_sq[s][chunk]  = tq;
    }
}

// block 0: finalize stats; block 1: build B fragments (independent work merged)
__global__ void stats_final_bfrag(const float* __restrict__ wgt) {
    if (blockIdx.x == 0) {
        if (threadIdx.x < 32) {
            const int s = threadIdx.x;
            float sum = 0.f, sq = 0.f;
            #pragma unroll
            for (int i = 0; i < NCHUNK; i++) {
                sum += g_partial_sum[s][i];
                sq  += g_partial_sq[s][i];
            }
            const float inv = 1.0f / (float)PLANE;
            const float mean = sum * inv;
            const float var = sq * inv - mean * mean;
            g_mean[s] = mean;
            g_rstd[s] = rsqrtf(var + EPS);
        }
    } else {
        for (int e = threadIdx.x; e < 1728; e += 256) {
            const int l = e & 31;
            const int P = (e >> 5) & 1;
            const int tap = (e >> 6) % 9;
            const int tt = e / (9 * 64);
            const int kd = tap / 3, kh = tap % 3;
            const int co = l >> 2;
            float f[4];
            #pragma unroll
            for (int j = 0; j < 2; j++)
                #pragma unroll
                for (int hv = 0; hv < 2; hv++) {
                    const int k = j * 8 + (l & 3) * 2 + hv;
                    const int pt = k >> 2, ci = k & 3;
                    const int kw = pt - P;
                    f[j * 2 + hv] = (kw >= 0 && kw < 3)
                        ? wgt[(co * CI + ci) * 81 + tt * 27 + kd * 9 + kh * 3 + kw]
                        : 0.f;
                }
            half2 h0 = __floats2half2_rn(f[0], f[1]);
            half2 h1 = __floats2half2_rn(f[2], f[3]);
            uint2 v;
            v.x = *(uint32_t*)&h0;
            v.y = *(uint32_t*)&h1;
            g_bfrag[tt][tap][P][l] = v;
        }
    }
}

// ---------------- prepass: normalize + ReLU + f16 pack (vectorized x4) ----
__global__ __launch_bounds__(256)
void normalize_f16(const float* __restrict__ x) {
    const int d = blockIdx.x % DD, t = blockIdx.x / DD;
    float mean[CI], rstd[CI];
    #pragma unroll
    for (int ci = 0; ci < CI; ci++) {
        mean[ci] = g_mean[ci * TT_ + t];
        rstd[ci] = g_rstd[ci * TT_ + t];
    }
    const float* xb = x + (size_t)t * PLANE + (size_t)d * (HH * WW);
    // 9216 pts -> 2304 quads
    for (int q = threadIdx.x; q < (HH * WW) / 4; q += 256) {
        const int h = q / (WW / 4), wq = (q % (WW / 4)) * 4;
        const int i = h * WW + wq;
        const float4 v0 = *(const float4*)(xb + i);
        const float4 v1 = *(const float4*)(xb + i + 8  * PLANE);
        const float4 v2 = *(const float4*)(xb + i + 16 * PLANE);
        const float4 v3 = *(const float4*)(xb + i + 24 * PLANE);
        const float p0[4] = {v0.x, v0.y, v0.z, v0.w};
        const float p1[4] = {v1.x, v1.y, v1.z, v1.w};
        const float p2[4] = {v2.x, v2.y, v2.z, v2.w};
        const float p3[4] = {v3.x, v3.y, v3.z, v3.w};
        #pragma unroll
        for (int j = 0; j < 4; j++) {
            const float f0 = fmaxf(0.f, (p0[j] - mean[0]) * rstd[0]);
            const float f1 = fmaxf(0.f, (p1[j] - mean[1]) * rstd[1]);
            const float f2 = fmaxf(0.f, (p2[j] - mean[2]) * rstd[2]);
            const float f3 = fmaxf(0.f, (p3[j] - mean[3]) * rstd[3]);
            half2 h01 = __floats2half2_rn(f0, f1);
            half2 h23 = __floats2half2_rn(f2, f3);
            uint2 v;
            v.x = *(uint32_t*)&h01;
            v.y = *(uint32_t*)&h23;
            g_xn[t][d + 1][h + 1][wq + 1 + j] = v;
        }
    }
}

// ---------------- mma helpers ----------------
__device__ __forceinline__ uint32_t smem_u32(const void* p) {
    uint32_t a;
    asm("{ .reg .u64 t; cvta.to.shared.u64 t, %1; cvt.u32.u64 %0, t; }" : "=r"(a) : "l"(p));
    return a;
}
__device__ __forceinline__ void ldsm4(uint32_t& a0, uint32_t& a1, uint32_t& a2,
                                      uint32_t& a3, uint32_t addr) {
    asm volatile("ldmatrix.sync.aligned.m8n8.x4.shared.b16 {%0,%1,%2,%3}, [%4];"
                 : "=r"(a0), "=r"(a1), "=r"(a2), "=r"(a3) : "r"(addr));
}
__device__ __forceinline__ void mma_f16(float* d, uint32_t a0, uint32_t a1,
                                        uint32_t a2, uint32_t a3,
                                        uint32_t b0, uint32_t b1) {
    asm volatile(
        "mma.sync.aligned.m16n8k16.row.col.f32.f16.f16.f32 "
        "{%0,%1,%2,%3}, {%4,%5,%6,%7}, {%8,%9}, {%0,%1,%2,%3};"
        : "+f"(d[0]), "+f"(d[1]), "+f"(d[2]), "+f"(d[3])
        : "r"(a0), "r"(a1), "r"(a2), "r"(a3), "r"(b0), "r"(b1));
}
__device__ __forceinline__ void cpasync16(uint32_t dst, const void* src) {
    asm volatile("cp.async.cg.shared.global [%0], [%1], 16;"
                 :: "r"(dst), "l"(__cvta_generic_to_global(src)) : "memory");
}
__device__ __forceinline__ void cp_commit() {
    asm volatile("cp.async.commit_group;" ::: "memory");
}
template <int N>
__device__ __forceinline__ void cp_wait() {
    asm volatile("cp.async.wait_group %0;" :: "n"(N) : "memory");
}

// ---------------- conv kernel config ----------------
#define D_TILE 4
#define H_TILE 4
#define DL 6
#define HL 6
#define NROWS (DL * HL)            // 36 rows
#define ROW_PTS 100
#define ROWB (ROW_PTS * 8)         // 800 B
#define SLICE_BYTES (NROWS * ROWB) // 28800
#define N_CHUNK (NROWS * (ROW_PTS / 2))   // 1800
#define SMEM_TOTAL (2 * SLICE_BYTES)      // 57600
#define NTH 256

__global__ __launch_bounds__(NTH, 2)
void conv4d_mma(const float* __restrict__ bias, float* __restrict__ out) {
    extern __shared__ char smem[];
    const uint32_t sbase = smem_u32(smem);
    const int tid = threadIdx.x;
    const int wid = tid >> 5, lane = tid & 31;

    const int bh = blockIdx.x % 24, bd = blockIdx.x / 24;
    const int t = blockIdx.y;
    const int d0 = bd * D_TILE, h0 = bh * H_TILE;

    const uint32_t lane_off = (uint32_t)(((lane & 15) + (lane >> 4)) * 16);

    int phases[3], nph = 0;
    #pragma unroll
    for (int tt = 0; tt < 3; tt++) {
        const int tp = t + tt - 1;
        if (tp >= 0 && tp < TT_) phases[nph++] = tt;
    }

    auto issue_phase = [&](int tt, int buf) {
        const int tp = t + tt - 1;
        const uint32_t base = sbase + buf * SLICE_BYTES;
        #pragma unroll 1
        for (int i = tid; i < N_CHUNK; i += NTH) {
            const int row = i / 50;
            const int c = i - row * 50;
            const int dl = row / HL, hl = row - dl * HL;
            cpasync16(base + (uint32_t)(row * ROWB + c * 16),
                      &g_xn[tp][d0 + dl][h0 + hl][2 * c]);
        }
        cp_commit();
    };

    float acc[2][3][2][4];
    #pragma unroll
    for (int p = 0; p < 2; p++)
        #pragma unroll
        for (int w = 0; w < 3; w++)
            #pragma unroll
            for (int q = 0; q < 2; q++)
                #pragma unroll
                for (int r = 0; r < 4; r++) acc[p][w][q][r] = 0.f;

    issue_phase(phases[0], 0);
    if (nph > 1) issue_phase(phases[1], 1);

    const int pid = wid * 2;
    // (od,oh) row offsets for the two output rows this warp owns
    const uint32_t rowoff0 =
        (uint32_t)((((pid) >> 2) * HL + ((pid) & 3)) * ROWB);
    const uint32_t rowoff1 =
        (uint32_t)((((pid + 1) >> 2) * HL + ((pid + 1) & 3)) * ROWB);

    #pragma unroll 1
    for (int i = 0; i < nph; i++) {
        const int tt = phases[i];
        // hoist B-fragment LDGs above the pipeline wait (latency overlap)
        uint2 bf[9][2];
        #pragma unroll
        for (int tp9 = 0; tp9 < 9; tp9++) {
            bf[tp9][0] = g_bfrag[tt][tp9][0][lane];
            bf[tp9][1] = g_bfrag[tt][tp9][1][lane];
        }

        if (i < nph - 1) cp_wait<1>(); else cp_wait<0>();
        __syncthreads();

        const uint32_t bufb = sbase + (uint32_t)((i & 1) * SLICE_BYTES) + lane_off;
        const uint32_t base0 = bufb + rowoff0;
        const uint32_t base1 = bufb + rowoff1;

        // taps outermost; 12 independent accumulator chains inside each tap
        #pragma unroll
        for (int kd = 0; kd < 3; kd++) {
            #pragma unroll
            for (int kh = 0; kh < 3; kh++) {
                const uint32_t toff = (uint32_t)((kd * HL + kh) * ROWB);
                const uint2 bE = bf[kd * 3 + kh][0];
                const uint2 bO = bf[kd * 3 + kh][1];
                #pragma unroll
                for (int pp = 0; pp < 2; pp++) {
                    const uint32_t pbase = (pp ? base1 : base0) + toff;
                    #pragma unroll
                    for (int wc = 0; wc < 3; wc++) {
                        uint32_t a0, a1, a2, a3;
                        ldsm4(a0, a1, a2, a3, pbase + (uint32_t)(wc * 256));
                        mma_f16(acc[pp][wc][0], a0, a1, a2, a3, bE.x, bE.y);
                        mma_f16(acc[pp][wc][1], a0, a1, a2, a3, bO.x, bO.y);
                    }
                }
            }
        }

        if (i + 2 < nph) {
            __syncthreads();
            issue_phase(phases[i + 2], i & 1);
        }
    }

    // ---- epilogue ----
    const int co0 = (lane & 3) * 2;
    const float bv0 = bias[co0], bv1 = bias[co0 + 1];
    #pragma unroll
    for (int pp = 0; pp < 2; pp++) {
        const int od = (pid + pp) >> 2, oh = (pid + pp) & 3;
        const int gd = d0 + od, gh = h0 + oh;
        #pragma unroll
        for (int wc = 0; wc < 3; wc++) {
            const int wb = wc * 32 + 2 * (lane >> 2);
            const size_t sp = (((size_t)t * DD + gd) * HH + gh) * WW + wb;
            const float* aE = acc[pp][wc][0];
            const float* aO = acc[pp][wc][1];
            float2 v;
            v.x = aE[0] + bv0; v.y = aO[0] + bv0;
            *(float2*)(out + (size_t)co0 * (TT_ * PLANE) + sp) = v;
            v.x = aE[1] + bv1; v.y = aO[1] + bv1;
            *(float2*)(out + (size_t)(co0 + 1) * (TT_ * PLANE) + sp) = v;
            v.x = aE[2] + bv0; v.y = aO[2] + bv0;
            *(float2*)(out + (size_t)co0 * (TT_ * PLANE) + sp + 16) = v;
            v.x = aE[3] + bv1; v.y = aO[3] + bv1;
            *(float2*)(out + (size_t)(co0 + 1) * (TT_ * PLANE) + sp + 16) = v;
        }
    }
}

// ---------------------------------------------------------------------------
extern "C" void kernel_launch(void* const* d_in, const int* in_sizes, int n_in,
                              void* d_out, int out_size) {
    const float* x = (const float*)d_in[0];
    const float* w = (const float*)d_in[1];
    const float* b = (const float*)d_in[2];
    float* out = (float*)d_out;

    cudaFuncSetAttribute(conv4d_mma, cudaFuncAttributeMaxDynamicSharedMemorySize,
                         SMEM_TOTAL);

    stats_partial<<<dim3(32, NCHUNK), 256>>>(x);
    stats_final_bfrag<<<2, 256>>>(w);
    normalize_f16<<<TT_ * DD, 256>>>(x);
    conv4d_mma<<<dim3(24 * 24, TT_), NTH, SMEM_TOTAL>>>(b, out);
}